// round 13
// baseline (speedup 1.0000x reference)
#include <cuda_runtime.h>
#include <cuda_bf16.h>
#include <math.h>
#include <stdint.h>
#include <mma.h>

using namespace nvcuda;

#define Bn 8
#define Ln 8192
#define Wn 128
#define MODESn 32
#define NLn 4
#define SEGn 4
#define CMn 8
#define LSn 2048
#define J2 64
#define SPLITS 64
#define LDG_ 136                 // gemm smem tile stride (bf16 elems)
#define LDD_ 40                  // dft smem tile stride (bf16 elems)

#define GEMM_TILE (16 * LDG_)                 // 2176 elems
#define GEMM_BUF  (4 * GEMM_TILE)             // 8704 elems (Ahi Alo Bhi Blo)
#define SF_PLANE  (128 * LDG_)                // 17408 elems
#define LAYER_SMEM ((4 * GEMM_BUF + 2 * SF_PLANE) * 2)   // 139264 B
#define FC_SMEM   (4 * GEMM_BUF * 2)          // 69632 B
#define DFT_ATILE (128 * LDD_)                // 5120
#define DFT_BTILE (64 * LDD_)                 // 2560
#define DFT_BUF   (2 * DFT_ATILE + 2 * DFT_BTILE)  // 15360
#define DFT_SMEM  (2 * DFT_BUF * 2)           // 61440 B

typedef wmma::fragment<wmma::matrix_a,16,16,16,__nv_bfloat16,wmma::col_major> FAc;
typedef wmma::fragment<wmma::matrix_a,16,16,16,__nv_bfloat16,wmma::row_major> FAr;
typedef wmma::fragment<wmma::matrix_b,16,16,16,__nv_bfloat16,wmma::row_major> FBr;
typedef wmma::fragment<wmma::matrix_b,16,16,16,__nv_bfloat16,wmma::col_major> FBc;
typedef wmma::fragment<wmma::accumulator,16,16,16,float> FC;

// ---------------- device scratch: bf16 hi/lo planes ----------------
__device__ __nv_bfloat16 g_h_hi[Bn*Wn*Ln], g_h_lo[Bn*Wn*Ln];     // [b][c][l]
__device__ __nv_bfloat16 g_bas_hi[J2*Ln], g_bas_lo[J2*Ln];       // [j][l]
__device__ __nv_bfloat16 g_sp_hi[Bn*J2*Wn], g_sp_lo[Bn*J2*Wn];   // [b][j][o]
__device__ __nv_bfloat16 g_w_hi[9*Wn*Wn], g_w_lo[9*Wn*Wn];       // [m][c][o]
__device__ float g_part[SPLITS*Bn*Wn*J2];                        // 16.8 MB
__device__ float g_cpart[SPLITS*Bn*Wn*CMn];                      // 2 MB
__device__ float g_hf2[Bn*Wn*J2];
__device__ float g_rec[Bn*Wn*SEGn];
__device__ float g_g2v[Bn*Wn*SEGn];
__device__ float g_wbar[NLn*SEGn*CMn*Wn];
__device__ float g_mn[SEGn];
__device__ float g_mx[SEGn];

// ---------------- helpers ----------------
__device__ __forceinline__ float gelu_exact(float v) {
    return 0.5f * v * (1.0f + erff(v * 0.70710678118654752f));
}
__device__ __forceinline__ void split1(float v, __nv_bfloat16* hi, __nv_bfloat16* lo) {
    __nv_bfloat16 h = __float2bfloat16(v);
    *hi = h;
    *lo = __float2bfloat16(v - __bfloat162float(h));
}
__device__ __forceinline__ void split8_store(const float* v, __nv_bfloat16* hi,
                                             __nv_bfloat16* lo) {
    __nv_bfloat16 hb[8], lb[8];
#pragma unroll
    for (int j = 0; j < 8; j++) {
        __nv_bfloat16 h = __float2bfloat16(v[j]);
        hb[j] = h;
        lb[j] = __float2bfloat16(v[j] - __bfloat162float(h));
    }
    *(uint4*)hi = *(uint4*)hb;
    *(uint4*)lo = *(uint4*)lb;
}
__device__ __forceinline__ uint32_t smem_u32(const void* p) {
    uint32_t a;
    asm("{ .reg .u64 t; cvta.to.shared.u64 t, %1; cvt.u32.u64 %0, t; }" : "=r"(a) : "l"(p));
    return a;
}
__device__ __forceinline__ void cpa16(uint32_t s, const void* g) {
    asm volatile("cp.async.cg.shared.global [%0], [%1], 16;" :: "r"(s), "l"(g));
}
#define CP_COMMIT() asm volatile("cp.async.commit_group;" ::: "memory")
#define CP_WAIT2()  asm volatile("cp.async.wait_group 2;" ::: "memory")
#define CP_WAIT1()  asm volatile("cp.async.wait_group 1;" ::: "memory")
#define CP_WAIT0()  asm volatile("cp.async.wait_group 0;" ::: "memory")

__device__ __forceinline__ void atomicMinF(float* addr, float v) {
    int* ia = (int*)addr; int old = *ia;
    while (__int_as_float(old) > v) {
        int assumed = old;
        old = atomicCAS(ia, assumed, __float_as_int(v));
        if (old == assumed) break;
    }
}
__device__ __forceinline__ void atomicMaxF(float* addr, float v) {
    int* ia = (int*)addr; int old = *ia;
    while (__int_as_float(old) < v) {
        int assumed = old;
        old = atomicCAS(ia, assumed, __float_as_int(v));
        if (old == assumed) break;
    }
}

// stage a hi/lo pair of tiles: rows x (c16*8 bf16), src stride in elems
__device__ __forceinline__ void stage2(uint32_t dhi, uint32_t dlo,
        const __nv_bfloat16* __restrict__ shi, const __nv_bfloat16* __restrict__ slo,
        long stride, int rows, int c16, int ld) {
    int n = rows * c16;
    for (int i = threadIdx.x; i < n; i += 256) {
        int r = i / c16, q = i - r * c16;
        uint32_t off = (uint32_t)(r * ld + q * 8) * 2;
        long gix = (long)r * stride + q * 8;
        cpa16(dhi + off, shi + gix);
        cpa16(dlo + off, slo + gix);
    }
}

// ---------------- small scalar kernels ----------------
__global__ void k_basis() {
    int t = blockIdx.x * blockDim.x + threadIdx.x;   // MODES*L
    int k = t / Ln, l = t % Ln;
    float x = (float)(k * l) * (1.0f / 4096.0f);
    float s, c;
    sincospif(x, &s, &c);
    split1(c, &g_bas_hi[k * Ln + l], &g_bas_lo[k * Ln + l]);
    split1(s, &g_bas_hi[(MODESn + k) * Ln + l], &g_bas_lo[(MODESn + k) * Ln + l]);
}

__global__ void k_wbar(const float* __restrict__ cheb_w) {
    int ism = blockIdx.x;
    int c = threadIdx.x;
    const float* p = cheb_w + ((long)ism * Wn + c) * Wn;
    float s = 0.f;
    for (int o = 0; o < Wn; o++) s += p[o];
    g_wbar[ism * Wn + c] = s * (1.0f / Wn);
}

__global__ void k_wsplit(const float* __restrict__ conv_w,
                         const float* __restrict__ gate_w,
                         const float* __restrict__ fc1_w) {
    int t = blockIdx.x * 256 + threadIdx.x;   // 9*128*128
    int m = t >> 14;
    int co = t & 16383;
    float v;
    if (m < 4)      v = conv_w[(long)m * 16384 + co];
    else if (m < 8) v = gate_w[(long)(m - 4) * 32768 + co];
    else            v = fc1_w[co];
    split1(v, &g_w_hi[t], &g_w_lo[t]);
}

__global__ void k_init_mnmx() {
    if (threadIdx.x < SEGn) { g_mn[threadIdx.x] = INFINITY; g_mx[threadIdx.x] = -INFINITY; }
}

// fc0 -> h planes [b][c][l], fused per-segment minmax
__global__ void k_fc0(const float* __restrict__ x, const float* __restrict__ w,
                      const float* __restrict__ bias) {
    __shared__ float smn[8], smx[8];
    long base = (long)blockIdx.x * 2048;
    float mn = INFINITY, mx = -INFINITY;
#pragma unroll
    for (int it = 0; it < 8; it++) {
        long t = base + it * 256 + threadIdx.x;
        int l = (int)(t & (Ln - 1));
        long bc = t >> 13;
        int c = (int)(bc & 127);
        long xb = ((bc >> 7) * Ln + l) * 2;
        float v = x[xb] * w[c] + x[xb + 1] * w[Wn + c] + bias[c];
        split1(v, &g_h_hi[t], &g_h_lo[t]);
        mn = fminf(mn, v); mx = fmaxf(mx, v);
    }
#pragma unroll
    for (int o = 16; o; o >>= 1) {
        mn = fminf(mn, __shfl_xor_sync(0xffffffffu, mn, o));
        mx = fmaxf(mx, __shfl_xor_sync(0xffffffffu, mx, o));
    }
    if ((threadIdx.x & 31) == 0) { smn[threadIdx.x >> 5] = mn; smx[threadIdx.x >> 5] = mx; }
    __syncthreads();
    if (threadIdx.x == 0) {
        for (int q = 1; q < 8; q++) { mn = fminf(mn, smn[q]); mx = fmaxf(mx, smx[q]); }
        int seg = (int)((base >> 11) & 3);
        atomicMinF(&g_mn[seg], mn);
        atomicMaxF(&g_mx[seg], mx);
    }
}

__global__ void k_dft_reduce() {
    int t = blockIdx.x * 256 + threadIdx.x;
    float s = 0.f;
#pragma unroll
    for (int q = 0; q < SPLITS; q++) s += g_part[(long)q * (Bn * Wn * J2) + t];
    g_hf2[t] = s;
}

__global__ void k_modemix(const float* __restrict__ wr, const float* __restrict__ wi,
                          int layer) {
    int b = blockIdx.y;
    int o = blockIdx.x * 8 + (threadIdx.x >> 5);
    int k = threadIdx.x & 31;
    const float* wrp = wr + (long)layer * Wn * Wn * MODESn;
    const float* wip = wi + (long)layer * Wn * Wn * MODESn;
    float omr = 0.f, omi = 0.f;
    for (int i = 0; i < Wn; i++) {
        float fr = g_hf2[(b * Wn + i) * J2 + k];
        float fs = g_hf2[(b * Wn + i) * J2 + 32 + k];
        long wix = ((long)i * Wn + o) * MODESn + k;
        float a = wrp[wix], bb = wip[wix];
        omr += fr * a + fs * bb;
        omi += fr * bb - fs * a;
    }
    float scale = ((k == 0) ? 1.0f : 2.0f) * (1.0f / Ln);
    int i0 = (b * J2 + k) * Wn + o;
    int i1 = (b * J2 + 32 + k) * Wn + o;
    split1(scale * omr, &g_sp_hi[i0], &g_sp_lo[i0]);
    split1(-scale * omi, &g_sp_hi[i1], &g_sp_lo[i1]);
}

// cheb reduce over splits + tanh -> rec, then g2 GEMV; also re-inits mn/mx
__global__ void k_chebg2(const float* __restrict__ gate_w, int layer) {
    __shared__ float srec[Wn];
    int s = blockIdx.x, b = blockIdx.y;
    int c = threadIdx.x;
    float a[CMn];
#pragma unroll
    for (int m = 0; m < CMn; m++) a[m] = 0.f;
#pragma unroll
    for (int sp = 0; sp < SPLITS / SEGn; sp++) {
        int split = s * (SPLITS / SEGn) + sp;
        const float* pp = g_cpart + (((long)split * Bn + b) * Wn + c) * CMn;
        float4 v0 = *(const float4*)pp;
        float4 v1 = *(const float4*)(pp + 4);
        a[0] += v0.x; a[1] += v0.y; a[2] += v0.z; a[3] += v0.w;
        a[4] += v1.x; a[5] += v1.y; a[6] += v1.z; a[7] += v1.w;
    }
    float r = 0.f;
#pragma unroll
    for (int m = 0; m < CMn; m++)
        r += (a[m] * (1.0f / LSn)) * g_wbar[((layer * SEGn + s) * CMn + m) * Wn + c];
    float rec = tanhf(r);
    srec[c] = rec;
    g_rec[(b * Wn + c) * SEGn + s] = rec;
    if (blockIdx.x == 0 && blockIdx.y == 0 && c < SEGn) {
        g_mn[c] = INFINITY; g_mx[c] = -INFINITY;
    }
    __syncthreads();
    int o = c;
    const float* gw = gate_w + (long)layer * 2 * Wn * Wn + Wn * Wn;
    float acc = 0.f;
#pragma unroll 4
    for (int cc = 0; cc < Wn; cc++)
        acc += srec[cc] * gw[cc * Wn + o];
    g_g2v[(b * Wn + o) * SEGn + s] = acc;
}

// ---------------- DFT + fused cheb partials (SPLITS=64, 128 l per split) ----------------
__global__ void __launch_bounds__(256) k_dft() {
    extern __shared__ __nv_bfloat16 smb[];
    const uint32_t sb = smem_u32(smb);
    const int split = blockIdx.x, b = blockIdx.y;
    const int tid = threadIdx.x;
    const int w = tid >> 5;
    const int wm = w >> 1, wn = w & 1;
    const long lbase = (long)split * 128;
    const int seg = split >> 4;
    const int cch = tid >> 1, half = tid & 1;   // cheb mapping
    const float mnv = g_mn[seg];
    const float scv = 2.0f / (g_mx[seg] - mnv);

    FC acc[2][2];
#pragma unroll
    for (int i = 0; i < 2; i++)
#pragma unroll
        for (int j = 0; j < 2; j++) wmma::fill_fragment(acc[i][j], 0.0f);
    float a[CMn];
#pragma unroll
    for (int m = 0; m < CMn; m++) a[m] = 0.f;

    auto stage_chunk = [&](int ci, int buf) {
        uint32_t base = sb + (uint32_t)buf * DFT_BUF * 2;
        long l0c = lbase + ci * 32;
        stage2(base, base + DFT_ATILE * 2,
               g_h_hi + ((long)b * Wn) * Ln + l0c, g_h_lo + ((long)b * Wn) * Ln + l0c,
               Ln, 128, 4, LDD_);
        stage2(base + 2 * DFT_ATILE * 2, base + 2 * DFT_ATILE * 2 + DFT_BTILE * 2,
               g_bas_hi + l0c, g_bas_lo + l0c, Ln, 64, 4, LDD_);
    };

    stage_chunk(0, 0);
    CP_COMMIT();
    for (int ci = 0; ci < 4; ci++) {
        int cur = ci & 1;
        if (ci < 3) {
            stage_chunk(ci + 1, cur ^ 1);
            CP_COMMIT();
            CP_WAIT1();
        } else {
            CP_WAIT0();
        }
        __syncthreads();
        const __nv_bfloat16* pa = smb + cur * DFT_BUF;
        const __nv_bfloat16* pb = pa + 2 * DFT_ATILE;
#pragma unroll
        for (int ks = 0; ks < 2; ks++) {
            FAr ah[2], al[2];
#pragma unroll
            for (int i = 0; i < 2; i++) {
                wmma::load_matrix_sync(ah[i], pa + (wm * 32 + i * 16) * LDD_ + ks * 16, LDD_);
                wmma::load_matrix_sync(al[i], pa + DFT_ATILE + (wm * 32 + i * 16) * LDD_ + ks * 16, LDD_);
            }
#pragma unroll
            for (int j = 0; j < 2; j++) {
                FBc bh, bl;
                wmma::load_matrix_sync(bh, pb + (wn * 32 + j * 16) * LDD_ + ks * 16, LDD_);
                wmma::load_matrix_sync(bl, pb + DFT_BTILE + (wn * 32 + j * 16) * LDD_ + ks * 16, LDD_);
#pragma unroll
                for (int i = 0; i < 2; i++) {
                    wmma::mma_sync(acc[i][j], ah[i], bh, acc[i][j]);
                    wmma::mma_sync(acc[i][j], ah[i], bl, acc[i][j]);
                    wmma::mma_sync(acc[i][j], al[i], bh, acc[i][j]);
                }
            }
        }
        // cheb partial pass over the same staged chunk (c = cch, 16 l values)
        {
            const __nv_bfloat16* hrow = pa + cch * LDD_ + half * 16;
            const __nv_bfloat16* lrow = hrow + DFT_ATILE;
#pragma unroll
            for (int j = 0; j < 16; j++) {
                float v = __bfloat162float(hrow[j]) + __bfloat162float(lrow[j]);
                float xn = (v - mnv) * scv - 1.0f;
                float Tpp = 1.0f, Tp = xn;
                a[0] += xn;
                a[1] += xn * xn;
#pragma unroll
                for (int m = 2; m < CMn; m++) {
                    float Tn = 2.0f * xn * Tp - Tpp;
                    a[m] += xn * Tn;
                    Tpp = Tp; Tp = Tn;
                }
            }
        }
        __syncthreads();
    }
#pragma unroll
    for (int m = 0; m < CMn; m++) a[m] += __shfl_xor_sync(0xffffffffu, a[m], 1);
    if (half == 0) {
        float* dst = g_cpart + (((long)split * Bn + b) * Wn + cch) * CMn;
        *(float4*)dst = make_float4(a[0], a[1], a[2], a[3]);
        *(float4*)(dst + 4) = make_float4(a[4], a[5], a[6], a[7]);
    }
#pragma unroll
    for (int i = 0; i < 2; i++)
#pragma unroll
        for (int j = 0; j < 2; j++)
            wmma::store_matrix_sync(
                g_part + (((long)split * Bn + b) * Wn + wm * 32 + i * 16) * J2 + wn * 32 + j * 16,
                acc[i][j], J2, wmma::mem_row_major);
}

// ---------------- fused layer kernel: 4-stage ring, 1 sync per chunk ----------------
__global__ void __launch_bounds__(256) k_layer(int layer,
        const float* __restrict__ conv_b, const float* __restrict__ gate_b) {
    extern __shared__ __nv_bfloat16 smb[];
    __shared__ float redmn[8], redmx[8];
    const uint32_t sb = smem_u32(smb);
    __nv_bfloat16* SFhi = smb + 4 * GEMM_BUF;
    __nv_bfloat16* SFlo = SFhi + SF_PLANE;

    const int b = blockIdx.y, l0 = blockIdx.x * 128;
    const int tid = threadIdx.x, w = tid >> 5, ln = tid & 31;
    const int wm = w >> 1, wn = w & 1;
    const int seg = l0 >> 11;
    const int r = ln >> 1, c0 = (ln & 1) * 8;
    const float* bias1 = conv_b + (long)layer * Wn;
    const float* bias2 = gate_b + (long)layer * Wn;
    const __nv_bfloat16* W1hi = g_w_hi + (long)layer * Wn * Wn;
    const __nv_bfloat16* W1lo = g_w_lo + (long)layer * Wn * Wn;
    const __nv_bfloat16* W2hi = g_w_hi + (long)(4 + layer) * Wn * Wn;
    const __nv_bfloat16* W2lo = g_w_lo + (long)(4 + layer) * Wn * Wn;

    FC acc[2][4];
#pragma unroll
    for (int i = 0; i < 2; i++)
#pragma unroll
        for (int j = 0; j < 4; j++) wmma::fill_fragment(acc[i][j], 0.0f);

    auto stage1 = [&](int ci, int buf) {
        uint32_t base = sb + (uint32_t)buf * GEMM_BUF * 2;
        const __nv_bfloat16 *ah, *al, *bh, *bl;
        if (ci < 8) {
            ah = W1hi + (long)ci * 16 * Wn; al = W1lo + (long)ci * 16 * Wn;
            bh = g_h_hi + ((long)(b * Wn + ci * 16)) * Ln + l0;
            bl = g_h_lo + ((long)(b * Wn + ci * 16)) * Ln + l0;
        } else {
            ah = g_sp_hi + ((long)b * J2 + (ci - 8) * 16) * Wn;
            al = g_sp_lo + ((long)b * J2 + (ci - 8) * 16) * Wn;
            bh = g_bas_hi + (long)((ci - 8) * 16) * Ln + l0;
            bl = g_bas_lo + (long)((ci - 8) * 16) * Ln + l0;
        }
        stage2(base, base + GEMM_TILE * 2, ah, al, Wn, 16, 16, LDG_);
        stage2(base + 2 * GEMM_TILE * 2, base + 3 * GEMM_TILE * 2, bh, bl, Ln, 16, 16, LDG_);
    };

    // ---- part 1 mainloop: K = 192 (12 chunks), 4-stage ring, 1 sync/chunk ----
    stage1(0, 0); CP_COMMIT();
    stage1(1, 1); CP_COMMIT();
    for (int ci = 0; ci < 12; ci++) {
        if (ci + 2 < 12) {
            stage1(ci + 2, (ci + 2) & 3);
            CP_COMMIT();
            CP_WAIT2();
        } else if (ci + 1 < 12) {
            CP_WAIT1();
        } else {
            CP_WAIT0();
        }
        __syncthreads();
        const __nv_bfloat16* pa = smb + (ci & 3) * GEMM_BUF;
        const __nv_bfloat16* pb = pa + 2 * GEMM_TILE;
        FAc ah[2], al[2];
#pragma unroll
        for (int i = 0; i < 2; i++) {
            wmma::load_matrix_sync(ah[i], pa + wm * 32 + i * 16, LDG_);
            wmma::load_matrix_sync(al[i], pa + GEMM_TILE + wm * 32 + i * 16, LDG_);
        }
#pragma unroll
        for (int j = 0; j < 4; j++) {
            FBr bh, bl;
            wmma::load_matrix_sync(bh, pb + wn * 64 + j * 16, LDG_);
            wmma::load_matrix_sync(bl, pb + GEMM_TILE + wn * 64 + j * 16, LDG_);
#pragma unroll
            for (int i = 0; i < 2; i++) {
                wmma::mma_sync(acc[i][j], ah[i], bh, acc[i][j]);
                wmma::mma_sync(acc[i][j], ah[i], bl, acc[i][j]);
                wmma::mma_sync(acc[i][j], al[i], bh, acc[i][j]);
            }
        }
    }
    __syncthreads();   // all reads of stage buffers done before reuse

    // prefetch gate chunks 0,1 into buf0,buf1 (A slots); overlap with epilogue 1
    stage2(sb, sb + GEMM_TILE * 2, W2hi, W2lo, Wn, 16, 16, LDG_);
    CP_COMMIT();
    stage2(sb + GEMM_BUF * 2, sb + GEMM_BUF * 2 + GEMM_TILE * 2,
           W2hi + (long)16 * Wn, W2lo + (long)16 * Wn, Wn, 16, 16, LDG_);
    CP_COMMIT();

    // ---- epilogue 1: gelu -> SF smem tile (patch area = buf2 region) ----
    {
        float* patchw = (float*)(smb + 2 * GEMM_BUF) + w * 384;
#pragma unroll
        for (int i = 0; i < 2; i++) {
            int o = wm * 32 + i * 16 + r;
            float bi = bias1[o];
#pragma unroll
            for (int j = 0; j < 4; j++) {
                wmma::store_matrix_sync(patchw, acc[i][j], 24, wmma::mem_row_major);
                __syncwarp();
                float vals[8];
#pragma unroll
                for (int jj = 0; jj < 8; jj++)
                    vals[jj] = gelu_exact(patchw[r * 24 + c0 + jj] + bi);
                int lc = wn * 64 + j * 16 + c0;
                split8_store(vals, SFhi + o * LDG_ + lc, SFlo + o * LDG_ + lc);
                __syncwarp();
            }
        }
    }
    __syncthreads();   // SF visible; patch region free

    // ---- part 2 mainloop: gate GEMM, A staged (4-stage ring), B from SF ----
#pragma unroll
    for (int i = 0; i < 2; i++)
#pragma unroll
        for (int j = 0; j < 4; j++) wmma::fill_fragment(acc[i][j], 0.0f);

    for (int ci = 0; ci < 8; ci++) {
        if (ci + 2 < 8) {
            uint32_t base = sb + (uint32_t)((ci + 2) & 3) * GEMM_BUF * 2;
            stage2(base, base + GEMM_TILE * 2,
                   W2hi + (long)(ci + 2) * 16 * Wn, W2lo + (long)(ci + 2) * 16 * Wn,
                   Wn, 16, 16, LDG_);
            CP_COMMIT();
            CP_WAIT2();
        } else if (ci + 1 < 8) {
            CP_WAIT1();
        } else {
            CP_WAIT0();
        }
        __syncthreads();
        const __nv_bfloat16* pa = smb + (ci & 3) * GEMM_BUF;
        FAc ah[2], al[2];
#pragma unroll
        for (int i = 0; i < 2; i++) {
            wmma::load_matrix_sync(ah[i], pa + wm * 32 + i * 16, LDG_);
            wmma::load_matrix_sync(al[i], pa + GEMM_TILE + wm * 32 + i * 16, LDG_);
        }
#pragma unroll
        for (int j = 0; j < 4; j++) {
            FBr bh, bl;
            wmma::load_matrix_sync(bh, SFhi + ci * 16 * LDG_ + wn * 64 + j * 16, LDG_);
            wmma::load_matrix_sync(bl, SFlo + ci * 16 * LDG_ + wn * 64 + j * 16, LDG_);
#pragma unroll
            for (int i = 0; i < 2; i++) {
                wmma::mma_sync(acc[i][j], ah[i], bh, acc[i][j]);
                wmma::mma_sync(acc[i][j], ah[i], bl, acc[i][j]);
                wmma::mma_sync(acc[i][j], al[i], bh, acc[i][j]);
            }
        }
    }
    __syncthreads();

    // ---- epilogue 2: gate + residual -> g_h planes, minmax (patch = buf0 region) ----
    float* patch2 = (float*)smb + w * 384;
    float mnv = INFINITY, mxv = -INFINITY;
#pragma unroll
    for (int i = 0; i < 2; i++) {
        int o = wm * 32 + i * 16 + r;
        float gadd = bias2[o] + g_g2v[(b * Wn + o) * SEGn + seg];
        float rc = g_rec[(b * Wn + o) * SEGn + seg];
#pragma unroll
        for (int j = 0; j < 4; j++) {
            wmma::store_matrix_sync(patch2, acc[i][j], 24, wmma::mem_row_major);
            __syncwarp();
            int lc = wn * 64 + j * 16 + c0;
            uint4 rh = *(const uint4*)(SFhi + o * LDG_ + lc);
            uint4 rl = *(const uint4*)(SFlo + o * LDG_ + lc);
            const __nv_bfloat16* hp = (const __nv_bfloat16*)&rh;
            const __nv_bfloat16* lp = (const __nv_bfloat16*)&rl;
            float vals[8];
#pragma unroll
            for (int jj = 0; jj < 8; jj++) {
                float fn = __bfloat162float(hp[jj]) + __bfloat162float(lp[jj]);
                float aa = patch2[r * 24 + c0 + jj] + gadd;
                float v = fn + rc / (1.0f + expf(-aa));
                vals[jj] = v;
                mnv = fminf(mnv, v); mxv = fmaxf(mxv, v);
            }
            long gi = ((long)(b * Wn + o)) * Ln + l0 + lc;
            split8_store(vals, &g_h_hi[gi], &g_h_lo[gi]);
            __syncwarp();
        }
    }
#pragma unroll
    for (int s = 16; s; s >>= 1) {
        mnv = fminf(mnv, __shfl_xor_sync(0xffffffffu, mnv, s));
        mxv = fmaxf(mxv, __shfl_xor_sync(0xffffffffu, mxv, s));
    }
    if (ln == 0) { redmn[w] = mnv; redmx[w] = mxv; }
    __syncthreads();
    if (tid == 0) {
        for (int q = 1; q < 8; q++) {
            mnv = fminf(mnv, redmn[q]); mxv = fmaxf(mxv, redmx[q]);
        }
        atomicMinF(&g_mn[seg], mnv);
        atomicMaxF(&g_mx[seg], mxv);
    }
}

// ---------------- fc1+fc2 fused: 4-stage ring, 1 sync per chunk ----------------
__global__ void __launch_bounds__(256) k_fc12(
        const float* __restrict__ bias, const float* __restrict__ w2,
        const float* __restrict__ b2, float* __restrict__ outp) {
    extern __shared__ __nv_bfloat16 smb[];
    __shared__ __align__(32) float patch[8][16][24];
    __shared__ float WP[8][16];
    const uint32_t sb = smem_u32(smb);

    const int b = blockIdx.y, l0 = blockIdx.x * 128;
    const int tid = threadIdx.x, w = tid >> 5, ln = tid & 31;
    const __nv_bfloat16* Whi = g_w_hi + (long)8 * Wn * Wn;
    const __nv_bfloat16* Wlo = g_w_lo + (long)8 * Wn * Wn;

    FC acc[8];
#pragma unroll
    for (int n = 0; n < 8; n++) wmma::fill_fragment(acc[n], 0.0f);

    auto stage_chunk = [&](int ci, int buf) {
        uint32_t base = sb + (uint32_t)buf * GEMM_BUF * 2;
        stage2(base, base + GEMM_TILE * 2,
               Whi + (long)ci * 16 * Wn, Wlo + (long)ci * 16 * Wn, Wn, 16, 16, LDG_);
        stage2(base + 2 * GEMM_TILE * 2, base + 3 * GEMM_TILE * 2,
               g_h_hi + ((long)(b * Wn + ci * 16)) * Ln + l0,
               g_h_lo + ((long)(b * Wn + ci * 16)) * Ln + l0, Ln, 16, 16, LDG_);
    };

    stage_chunk(0, 0); CP_COMMIT();
    stage_chunk(1, 1); CP_COMMIT();
    for (int ci = 0; ci < 8; ci++) {
        if (ci + 2 < 8) {
            stage_chunk(ci + 2, (ci + 2) & 3);
            CP_COMMIT();
            CP_WAIT2();
        } else if (ci + 1 < 8) {
            CP_WAIT1();
        } else {
            CP_WAIT0();
        }
        __syncthreads();
        const __nv_bfloat16* pa = smb + (ci & 3) * GEMM_BUF;
        const __nv_bfloat16* pb = pa + 2 * GEMM_TILE;
        FAc ah, al;
        wmma::load_matrix_sync(ah, pa + w * 16, LDG_);
        wmma::load_matrix_sync(al, pa + GEMM_TILE + w * 16, LDG_);
#pragma unroll
        for (int n = 0; n < 8; n++) {
            FBr bh, bl;
            wmma::load_matrix_sync(bh, pb + n * 16, LDG_);
            wmma::load_matrix_sync(bl, pb + GEMM_TILE + n * 16, LDG_);
            wmma::mma_sync(acc[n], ah, bh, acc[n]);
            wmma::mma_sync(acc[n], ah, bl, acc[n]);
            wmma::mma_sync(acc[n], al, bh, acc[n]);
        }
    }
    __syncthreads();

    const int r = ln >> 1, c0 = (ln & 1) * 8;
    const int o = w * 16 + r;
    const float bi = bias[o], w2v = w2[o];
#pragma unroll
    for (int n = 0; n < 8; n++) {
        wmma::store_matrix_sync(&patch[w][0][0], acc[n], 24, wmma::mem_row_major);
        __syncwarp();
        float vals[8];
#pragma unroll
        for (int j = 0; j < 8; j++)
            vals[j] = gelu_exact(patch[w][r][c0 + j] + bi) * w2v;
#pragma unroll
        for (int s = 2; s <= 16; s <<= 1)
#pragma unroll
            for (int j = 0; j < 8; j++)
                vals[j] += __shfl_xor_sync(0xffffffffu, vals[j], s);
        if (ln < 2)
#pragma unroll
            for (int j = 0; j < 8; j++) WP[w][ln * 8 + j] = vals[j];
        __syncthreads();
        if (tid < 16) {
            float t = 0.f;
#pragma unroll
            for (int q = 0; q < 8; q++) t += WP[q][tid];
            outp[(long)b * Ln + l0 + n * 16 + tid] = t + b2[0];
        }
        __syncthreads();
    }
}

// ---------------- launch ----------------
extern "C" void kernel_launch(void* const* d_in, const int* in_sizes, int n_in,
                              void* d_out, int out_size) {
    const float* x       = (const float*)d_in[0];
    const float* fc0_w   = (const float*)d_in[1];
    const float* fc0_b   = (const float*)d_in[2];
    const float* spec_wr = (const float*)d_in[3];
    const float* spec_wi = (const float*)d_in[4];
    const float* conv_w  = (const float*)d_in[5];
    const float* conv_b  = (const float*)d_in[6];
    const float* cheb_w  = (const float*)d_in[7];
    const float* gate_w  = (const float*)d_in[8];
    const float* gate_b  = (const float*)d_in[9];
    const float* fc1_w   = (const float*)d_in[10];
    const float* fc1_b   = (const float*)d_in[11];
    const float* fc2_w   = (const float*)d_in[12];
    const float* fc2_b   = (const float*)d_in[13];

    cudaFuncSetAttribute(k_dft,   cudaFuncAttributeMaxDynamicSharedMemorySize, DFT_SMEM);
    cudaFuncSetAttribute(k_layer, cudaFuncAttributeMaxDynamicSharedMemorySize, LAYER_SMEM);
    cudaFuncSetAttribute(k_fc12,  cudaFuncAttributeMaxDynamicSharedMemorySize, FC_SMEM);

    k_init_mnmx<<<1, 32>>>();
    k_fc0<<<(Bn * Wn * Ln) / 2048, 256>>>(x, fc0_w, fc0_b);
    k_basis<<<(MODESn * Ln) / 256, 256>>>();
    k_dft<<<dim3(SPLITS, Bn), 256, DFT_SMEM>>>();     // layer 0 DFT
    k_wbar<<<NLn * SEGn * CMn, 128>>>(cheb_w);
    k_wsplit<<<(9 * Wn * Wn) / 256, 256>>>(conv_w, gate_w, fc1_w);

    for (int i = 0; i < NLn; i++) {
        if (i > 0) k_dft<<<dim3(SPLITS, Bn), 256, DFT_SMEM>>>();
        k_dft_reduce<<<(Bn * Wn * J2) / 256, 256>>>();
        k_modemix<<<dim3(16, Bn), 256>>>(spec_wr, spec_wi, i);
        k_chebg2<<<dim3(SEGn, Bn), 128>>>(gate_w, i);
        k_layer<<<dim3(Ln / 128, Bn), 256, LAYER_SMEM>>>(i, conv_b, gate_b);
    }
    k_fc12<<<dim3(Ln / 128, Bn), 256, FC_SMEM>>>(fc1_b, fc2_w, fc2_b, (float*)d_out);
}

// round 14
// speedup vs baseline: 1.0519x; 1.0519x over previous
#include <cuda_runtime.h>
#include <cuda_bf16.h>
#include <math.h>
#include <stdint.h>
#include <mma.h>

using namespace nvcuda;

#define Bn 8
#define Ln 8192
#define Wn 128
#define MODESn 32
#define NLn 4
#define SEGn 4
#define CMn 8
#define LSn 2048
#define J2 64
#define SPLITS 32
#define LDG_ 136                 // gemm smem tile stride (bf16 elems)
#define LDD_ 40                  // dft smem tile stride (bf16 elems)

#define GEMM_TILE (16 * LDG_)                 // 2176 elems (16-row tile, fc12)
#define GEMM_BUF  (4 * GEMM_TILE)             // 8704 elems
#define LT32      (32 * LDG_)                 // 4352 elems (32-row tile, k_layer)
#define LB32      (4 * LT32)                  // 17408 elems (Ahi Alo Bhi Blo)
#define SF_PLANE  (128 * LDG_)                // 17408 elems
#define LAYER_SMEM ((2 * LB32 + 2 * SF_PLANE) * 2)   // 139264 B
#define FC_SMEM   (2 * GEMM_BUF * 2)          // 34816 B
#define DFT_ATILE (128 * LDD_)                // 5120
#define DFT_BTILE (64 * LDD_)                 // 2560
#define DFT_BUF   (2 * DFT_ATILE + 2 * DFT_BTILE)  // 15360
#define DFT_SMEM  (2 * DFT_BUF * 2)           // 61440 B

typedef wmma::fragment<wmma::matrix_a,16,16,16,__nv_bfloat16,wmma::col_major> FAc;
typedef wmma::fragment<wmma::matrix_a,16,16,16,__nv_bfloat16,wmma::row_major> FAr;
typedef wmma::fragment<wmma::matrix_b,16,16,16,__nv_bfloat16,wmma::row_major> FBr;
typedef wmma::fragment<wmma::matrix_b,16,16,16,__nv_bfloat16,wmma::col_major> FBc;
typedef wmma::fragment<wmma::accumulator,16,16,16,float> FC;

// ---------------- device scratch: bf16 hi/lo planes ----------------
__device__ __nv_bfloat16 g_h_hi[Bn*Wn*Ln], g_h_lo[Bn*Wn*Ln];     // [b][c][l]
__device__ __nv_bfloat16 g_bas_hi[J2*Ln], g_bas_lo[J2*Ln];       // [j][l]
__device__ __nv_bfloat16 g_sp_hi[Bn*J2*Wn], g_sp_lo[Bn*J2*Wn];   // [b][j][o]
__device__ __nv_bfloat16 g_w_hi[9*Wn*Wn], g_w_lo[9*Wn*Wn];       // [m][c][o]
__device__ float g_part[SPLITS*Bn*Wn*J2];                        // 8 MB
__device__ float g_cpart[SPLITS*Bn*Wn*CMn];                      // 1 MB
__device__ float g_hf2[Bn*Wn*J2];
__device__ float g_rec[Bn*Wn*SEGn];
__device__ float g_g2v[Bn*Wn*SEGn];
__device__ float g_wbar[NLn*SEGn*CMn*Wn];
__device__ float g_mn[SEGn];
__device__ float g_mx[SEGn];

// ---------------- helpers ----------------
__device__ __forceinline__ float gelu_exact(float v) {
    return 0.5f * v * (1.0f + erff(v * 0.70710678118654752f));
}
__device__ __forceinline__ void split1(float v, __nv_bfloat16* hi, __nv_bfloat16* lo) {
    __nv_bfloat16 h = __float2bfloat16(v);
    *hi = h;
    *lo = __float2bfloat16(v - __bfloat162float(h));
}
__device__ __forceinline__ void split8_store(const float* v, __nv_bfloat16* hi,
                                             __nv_bfloat16* lo) {
    __nv_bfloat16 hb[8], lb[8];
#pragma unroll
    for (int j = 0; j < 8; j++) {
        __nv_bfloat16 h = __float2bfloat16(v[j]);
        hb[j] = h;
        lb[j] = __float2bfloat16(v[j] - __bfloat162float(h));
    }
    *(uint4*)hi = *(uint4*)hb;
    *(uint4*)lo = *(uint4*)lb;
}
__device__ __forceinline__ uint32_t smem_u32(const void* p) {
    uint32_t a;
    asm("{ .reg .u64 t; cvta.to.shared.u64 t, %1; cvt.u32.u64 %0, t; }" : "=r"(a) : "l"(p));
    return a;
}
__device__ __forceinline__ void cpa16(uint32_t s, const void* g) {
    asm volatile("cp.async.cg.shared.global [%0], [%1], 16;" :: "r"(s), "l"(g));
}
#define CP_COMMIT() asm volatile("cp.async.commit_group;" ::: "memory")
#define CP_WAIT1()  asm volatile("cp.async.wait_group 1;" ::: "memory")
#define CP_WAIT0()  asm volatile("cp.async.wait_group 0;" ::: "memory")

__device__ __forceinline__ void atomicMinF(float* addr, float v) {
    int* ia = (int*)addr; int old = *ia;
    while (__int_as_float(old) > v) {
        int assumed = old;
        old = atomicCAS(ia, assumed, __float_as_int(v));
        if (old == assumed) break;
    }
}
__device__ __forceinline__ void atomicMaxF(float* addr, float v) {
    int* ia = (int*)addr; int old = *ia;
    while (__int_as_float(old) < v) {
        int assumed = old;
        old = atomicCAS(ia, assumed, __float_as_int(v));
        if (old == assumed) break;
    }
}

// stage a hi/lo pair of tiles: rows x (c16*8 bf16), src stride in elems
__device__ __forceinline__ void stage2(uint32_t dhi, uint32_t dlo,
        const __nv_bfloat16* __restrict__ shi, const __nv_bfloat16* __restrict__ slo,
        long stride, int rows, int c16, int ld) {
    int n = rows * c16;
    for (int i = threadIdx.x; i < n; i += 256) {
        int r = i / c16, q = i - r * c16;
        uint32_t off = (uint32_t)(r * ld + q * 8) * 2;
        long gix = (long)r * stride + q * 8;
        cpa16(dhi + off, shi + gix);
        cpa16(dlo + off, slo + gix);
    }
}

// ---------------- small scalar kernels ----------------
__global__ void k_basis() {
    int t = blockIdx.x * blockDim.x + threadIdx.x;   // MODES*L
    int k = t / Ln, l = t % Ln;
    float x = (float)(k * l) * (1.0f / 4096.0f);
    float s, c;
    sincospif(x, &s, &c);
    split1(c, &g_bas_hi[k * Ln + l], &g_bas_lo[k * Ln + l]);
    split1(s, &g_bas_hi[(MODESn + k) * Ln + l], &g_bas_lo[(MODESn + k) * Ln + l]);
}

__global__ void k_wbar(const float* __restrict__ cheb_w) {
    int ism = blockIdx.x;
    int c = threadIdx.x;
    const float* p = cheb_w + ((long)ism * Wn + c) * Wn;
    float s = 0.f;
    for (int o = 0; o < Wn; o++) s += p[o];
    g_wbar[ism * Wn + c] = s * (1.0f / Wn);
}

__global__ void k_wsplit(const float* __restrict__ conv_w,
                         const float* __restrict__ gate_w,
                         const float* __restrict__ fc1_w) {
    int t = blockIdx.x * 256 + threadIdx.x;   // 9*128*128
    int m = t >> 14;
    int co = t & 16383;
    float v;
    if (m < 4)      v = conv_w[(long)m * 16384 + co];
    else if (m < 8) v = gate_w[(long)(m - 4) * 32768 + co];
    else            v = fc1_w[co];
    split1(v, &g_w_hi[t], &g_w_lo[t]);
}

__global__ void k_init_mnmx() {
    if (threadIdx.x < SEGn) { g_mn[threadIdx.x] = INFINITY; g_mx[threadIdx.x] = -INFINITY; }
}

// fc0 -> h planes [b][c][l], fused per-segment minmax
__global__ void k_fc0(const float* __restrict__ x, const float* __restrict__ w,
                      const float* __restrict__ bias) {
    __shared__ float smn[8], smx[8];
    long base = (long)blockIdx.x * 2048;
    float mn = INFINITY, mx = -INFINITY;
#pragma unroll
    for (int it = 0; it < 8; it++) {
        long t = base + it * 256 + threadIdx.x;
        int l = (int)(t & (Ln - 1));
        long bc = t >> 13;
        int c = (int)(bc & 127);
        long xb = ((bc >> 7) * Ln + l) * 2;
        float v = x[xb] * w[c] + x[xb + 1] * w[Wn + c] + bias[c];
        split1(v, &g_h_hi[t], &g_h_lo[t]);
        mn = fminf(mn, v); mx = fmaxf(mx, v);
    }
#pragma unroll
    for (int o = 16; o; o >>= 1) {
        mn = fminf(mn, __shfl_xor_sync(0xffffffffu, mn, o));
        mx = fmaxf(mx, __shfl_xor_sync(0xffffffffu, mx, o));
    }
    if ((threadIdx.x & 31) == 0) { smn[threadIdx.x >> 5] = mn; smx[threadIdx.x >> 5] = mx; }
    __syncthreads();
    if (threadIdx.x == 0) {
        for (int q = 1; q < 8; q++) { mn = fminf(mn, smn[q]); mx = fmaxf(mx, smx[q]); }
        int seg = (int)((base >> 11) & 3);
        atomicMinF(&g_mn[seg], mn);
        atomicMaxF(&g_mx[seg], mx);
    }
}

__global__ void k_dft_reduce() {
    int t = blockIdx.x * 256 + threadIdx.x;
    float s = 0.f;
#pragma unroll
    for (int q = 0; q < SPLITS; q++) s += g_part[(long)q * (Bn * Wn * J2) + t];
    g_hf2[t] = s;
}

__global__ void k_modemix(const float* __restrict__ wr, const float* __restrict__ wi,
                          int layer) {
    int b = blockIdx.y;
    int o = blockIdx.x * 8 + (threadIdx.x >> 5);
    int k = threadIdx.x & 31;
    const float* wrp = wr + (long)layer * Wn * Wn * MODESn;
    const float* wip = wi + (long)layer * Wn * Wn * MODESn;
    float omr = 0.f, omi = 0.f;
    for (int i = 0; i < Wn; i++) {
        float fr = g_hf2[(b * Wn + i) * J2 + k];
        float fs = g_hf2[(b * Wn + i) * J2 + 32 + k];
        long wix = ((long)i * Wn + o) * MODESn + k;
        float a = wrp[wix], bb = wip[wix];
        omr += fr * a + fs * bb;
        omi += fr * bb - fs * a;
    }
    float scale = ((k == 0) ? 1.0f : 2.0f) * (1.0f / Ln);
    int i0 = (b * J2 + k) * Wn + o;
    int i1 = (b * J2 + 32 + k) * Wn + o;
    split1(scale * omr, &g_sp_hi[i0], &g_sp_lo[i0]);
    split1(-scale * omi, &g_sp_hi[i1], &g_sp_lo[i1]);
}

// cheb reduce over splits + tanh -> rec, then g2 GEMV; also re-inits mn/mx
__global__ void k_chebg2(const float* __restrict__ gate_w, int layer) {
    __shared__ float srec[Wn];
    int s = blockIdx.x, b = blockIdx.y;
    int c = threadIdx.x;
    float a[CMn];
#pragma unroll
    for (int m = 0; m < CMn; m++) a[m] = 0.f;
#pragma unroll
    for (int sp = 0; sp < 8; sp++) {
        int split = s * 8 + sp;
        const float* pp = g_cpart + (((long)split * Bn + b) * Wn + c) * CMn;
        float4 v0 = *(const float4*)pp;
        float4 v1 = *(const float4*)(pp + 4);
        a[0] += v0.x; a[1] += v0.y; a[2] += v0.z; a[3] += v0.w;
        a[4] += v1.x; a[5] += v1.y; a[6] += v1.z; a[7] += v1.w;
    }
    float r = 0.f;
#pragma unroll
    for (int m = 0; m < CMn; m++)
        r += (a[m] * (1.0f / LSn)) * g_wbar[((layer * SEGn + s) * CMn + m) * Wn + c];
    float rec = tanhf(r);
    srec[c] = rec;
    g_rec[(b * Wn + c) * SEGn + s] = rec;
    if (blockIdx.x == 0 && blockIdx.y == 0 && c < SEGn) {
        g_mn[c] = INFINITY; g_mx[c] = -INFINITY;
    }
    __syncthreads();
    int o = c;
    const float* gw = gate_w + (long)layer * 2 * Wn * Wn + Wn * Wn;
    float acc = 0.f;
#pragma unroll 4
    for (int cc = 0; cc < Wn; cc++)
        acc += srec[cc] * gw[cc * Wn + o];
    g_g2v[(b * Wn + o) * SEGn + s] = acc;
}

// ---------------- DFT + fused cheb partials ----------------
__global__ void __launch_bounds__(256) k_dft() {
    extern __shared__ __nv_bfloat16 smb[];
    const uint32_t sb = smem_u32(smb);
    const int split = blockIdx.x, b = blockIdx.y;
    const int tid = threadIdx.x;
    const int w = tid >> 5;
    const int wm = w >> 1, wn = w & 1;
    const long lbase = (long)split * 256;
    const int seg = split >> 3;
    const int cch = tid >> 1, half = tid & 1;   // cheb mapping
    const float mnv = g_mn[seg];
    const float scv = 2.0f / (g_mx[seg] - mnv);

    FC acc[2][2];
#pragma unroll
    for (int i = 0; i < 2; i++)
#pragma unroll
        for (int j = 0; j < 2; j++) wmma::fill_fragment(acc[i][j], 0.0f);
    float a[CMn];
#pragma unroll
    for (int m = 0; m < CMn; m++) a[m] = 0.f;

    auto stage_chunk = [&](int ci, int buf) {
        uint32_t base = sb + (uint32_t)buf * DFT_BUF * 2;
        long l0c = lbase + ci * 32;
        stage2(base, base + DFT_ATILE * 2,
               g_h_hi + ((long)b * Wn) * Ln + l0c, g_h_lo + ((long)b * Wn) * Ln + l0c,
               Ln, 128, 4, LDD_);
        stage2(base + 2 * DFT_ATILE * 2, base + 2 * DFT_ATILE * 2 + DFT_BTILE * 2,
               g_bas_hi + l0c, g_bas_lo + l0c, Ln, 64, 4, LDD_);
    };

    stage_chunk(0, 0);
    CP_COMMIT();
    for (int ci = 0; ci < 8; ci++) {
        int cur = ci & 1;
        if (ci < 7) {
            stage_chunk(ci + 1, cur ^ 1);
            CP_COMMIT();
            CP_WAIT1();
        } else {
            CP_WAIT0();
        }
        __syncthreads();
        const __nv_bfloat16* pa = smb + cur * DFT_BUF;
        const __nv_bfloat16* pb = pa + 2 * DFT_ATILE;
#pragma unroll
        for (int ks = 0; ks < 2; ks++) {
            FAr ah[2], al[2];
#pragma unroll
            for (int i = 0; i < 2; i++) {
                wmma::load_matrix_sync(ah[i], pa + (wm * 32 + i * 16) * LDD_ + ks * 16, LDD_);
                wmma::load_matrix_sync(al[i], pa + DFT_ATILE + (wm * 32 + i * 16) * LDD_ + ks * 16, LDD_);
            }
#pragma unroll
            for (int j = 0; j < 2; j++) {
                FBc bh, bl;
                wmma::load_matrix_sync(bh, pb + (wn * 32 + j * 16) * LDD_ + ks * 16, LDD_);
                wmma::load_matrix_sync(bl, pb + DFT_BTILE + (wn * 32 + j * 16) * LDD_ + ks * 16, LDD_);
#pragma unroll
                for (int i = 0; i < 2; i++) {
                    wmma::mma_sync(acc[i][j], ah[i], bh, acc[i][j]);
                    wmma::mma_sync(acc[i][j], ah[i], bl, acc[i][j]);
                    wmma::mma_sync(acc[i][j], al[i], bh, acc[i][j]);
                }
            }
        }
        // cheb partial pass over the same staged chunk (c = cch, 16 l values)
        {
            const __nv_bfloat16* hrow = pa + cch * LDD_ + half * 16;
            const __nv_bfloat16* lrow = hrow + DFT_ATILE;
#pragma unroll
            for (int j = 0; j < 16; j++) {
                float v = __bfloat162float(hrow[j]) + __bfloat162float(lrow[j]);
                float xn = (v - mnv) * scv - 1.0f;
                float Tpp = 1.0f, Tp = xn;
                a[0] += xn;
                a[1] += xn * xn;
#pragma unroll
                for (int m = 2; m < CMn; m++) {
                    float Tn = 2.0f * xn * Tp - Tpp;
                    a[m] += xn * Tn;
                    Tpp = Tp; Tp = Tn;
                }
            }
        }
        __syncthreads();
    }
#pragma unroll
    for (int m = 0; m < CMn; m++) a[m] += __shfl_xor_sync(0xffffffffu, a[m], 1);
    if (half == 0) {
        float* dst = g_cpart + (((long)split * Bn + b) * Wn + cch) * CMn;
        *(float4*)dst = make_float4(a[0], a[1], a[2], a[3]);
        *(float4*)(dst + 4) = make_float4(a[4], a[5], a[6], a[7]);
    }
#pragma unroll
    for (int i = 0; i < 2; i++)
#pragma unroll
        for (int j = 0; j < 2; j++)
            wmma::store_matrix_sync(
                g_part + (((long)split * Bn + b) * Wn + wm * 32 + i * 16) * J2 + wn * 32 + j * 16,
                acc[i][j], J2, wmma::mem_row_major);
}

// ---------------- fused layer kernel: K=32 chunks (half the syncs) ----------------
__global__ void __launch_bounds__(256) k_layer(int layer,
        const float* __restrict__ conv_b, const float* __restrict__ gate_b) {
    extern __shared__ __nv_bfloat16 smb[];
    __shared__ float redmn[8], redmx[8];
    const uint32_t sb = smem_u32(smb);
    __nv_bfloat16* SFhi = smb + 2 * LB32;
    __nv_bfloat16* SFlo = SFhi + SF_PLANE;

    const int b = blockIdx.y, l0 = blockIdx.x * 128;
    const int tid = threadIdx.x, w = tid >> 5, ln = tid & 31;
    const int wm = w >> 1, wn = w & 1;
    const int seg = l0 >> 11;
    const int r = ln >> 1, c0 = (ln & 1) * 8;
    const float* bias1 = conv_b + (long)layer * Wn;
    const float* bias2 = gate_b + (long)layer * Wn;
    const __nv_bfloat16* W1hi = g_w_hi + (long)layer * Wn * Wn;
    const __nv_bfloat16* W1lo = g_w_lo + (long)layer * Wn * Wn;
    const __nv_bfloat16* W2hi = g_w_hi + (long)(4 + layer) * Wn * Wn;
    const __nv_bfloat16* W2lo = g_w_lo + (long)(4 + layer) * Wn * Wn;

    FC acc[2][4];
#pragma unroll
    for (int i = 0; i < 2; i++)
#pragma unroll
        for (int j = 0; j < 4; j++) wmma::fill_fragment(acc[i][j], 0.0f);

    // stage one 32-deep chunk (A 32xWn from weights/spec, B 32x128 from h/basis)
    auto stage1 = [&](int ci, int buf) {
        uint32_t base = sb + (uint32_t)buf * LB32 * 2;
        const __nv_bfloat16 *ah, *al, *bh, *bl;
        if (ci < 4) {
            ah = W1hi + (long)ci * 32 * Wn; al = W1lo + (long)ci * 32 * Wn;
            bh = g_h_hi + ((long)(b * Wn + ci * 32)) * Ln + l0;
            bl = g_h_lo + ((long)(b * Wn + ci * 32)) * Ln + l0;
        } else {
            ah = g_sp_hi + ((long)b * J2 + (ci - 4) * 32) * Wn;
            al = g_sp_lo + ((long)b * J2 + (ci - 4) * 32) * Wn;
            bh = g_bas_hi + (long)((ci - 4) * 32) * Ln + l0;
            bl = g_bas_lo + (long)((ci - 4) * 32) * Ln + l0;
        }
        stage2(base, base + LT32 * 2, ah, al, Wn, 32, 16, LDG_);
        stage2(base + 2 * LT32 * 2, base + 3 * LT32 * 2, bh, bl, Ln, 32, 16, LDG_);
    };

    // ---- part 1 mainloop: K = 192 (6 chunks of 32) ----
    stage1(0, 0);
    CP_COMMIT();
    for (int ci = 0; ci < 6; ci++) {
        int cur = ci & 1;
        if (ci < 5) {
            stage1(ci + 1, cur ^ 1);
            CP_COMMIT();
            CP_WAIT1();
        } else {
            CP_WAIT0();
        }
        __syncthreads();
        const __nv_bfloat16* pa = smb + cur * LB32;
        const __nv_bfloat16* pb = pa + 2 * LT32;
#pragma unroll
        for (int kk = 0; kk < 2; kk++) {
            FAc ah[2], al[2];
#pragma unroll
            for (int i = 0; i < 2; i++) {
                wmma::load_matrix_sync(ah[i], pa + kk * 16 * LDG_ + wm * 32 + i * 16, LDG_);
                wmma::load_matrix_sync(al[i], pa + LT32 + kk * 16 * LDG_ + wm * 32 + i * 16, LDG_);
            }
#pragma unroll
            for (int j = 0; j < 4; j++) {
                FBr bh, bl;
                wmma::load_matrix_sync(bh, pb + kk * 16 * LDG_ + wn * 64 + j * 16, LDG_);
                wmma::load_matrix_sync(bl, pb + LT32 + kk * 16 * LDG_ + wn * 64 + j * 16, LDG_);
#pragma unroll
                for (int i = 0; i < 2; i++) {
                    wmma::mma_sync(acc[i][j], ah[i], bh, acc[i][j]);
                    wmma::mma_sync(acc[i][j], ah[i], bl, acc[i][j]);
                    wmma::mma_sync(acc[i][j], al[i], bh, acc[i][j]);
                }
            }
        }
        __syncthreads();
    }

    // prefetch gate chunk 0 (A only, 32 rows) into buf0
    stage2(sb, sb + LT32 * 2, W2hi, W2lo, Wn, 32, 16, LDG_);
    CP_COMMIT();

    // ---- epilogue 1: gelu -> SF smem tile (patch area = buf1 region) ----
    {
        float* patchw = (float*)(smb + LB32) + w * 384;
#pragma unroll
        for (int i = 0; i < 2; i++) {
            int o = wm * 32 + i * 16 + r;
            float bi = bias1[o];
#pragma unroll
            for (int j = 0; j < 4; j++) {
                wmma::store_matrix_sync(patchw, acc[i][j], 24, wmma::mem_row_major);
                __syncwarp();
                float vals[8];
#pragma unroll
                for (int jj = 0; jj < 8; jj++)
                    vals[jj] = gelu_exact(patchw[r * 24 + c0 + jj] + bi);
                int lc = wn * 64 + j * 16 + c0;
                split8_store(vals, SFhi + o * LDG_ + lc, SFlo + o * LDG_ + lc);
                __syncwarp();
            }
        }
    }
    __syncthreads();

    // ---- part 2 mainloop: gate GEMM (4 chunks of 32), B from SF ----
#pragma unroll
    for (int i = 0; i < 2; i++)
#pragma unroll
        for (int j = 0; j < 4; j++) wmma::fill_fragment(acc[i][j], 0.0f);

    for (int ci = 0; ci < 4; ci++) {
        int cur = ci & 1;
        if (ci < 3) {
            uint32_t base = sb + (uint32_t)(cur ^ 1) * LB32 * 2;
            stage2(base, base + LT32 * 2,
                   W2hi + (long)(ci + 1) * 32 * Wn, W2lo + (long)(ci + 1) * 32 * Wn,
                   Wn, 32, 16, LDG_);
            CP_COMMIT();
            CP_WAIT1();
        } else {
            CP_WAIT0();
        }
        __syncthreads();
        const __nv_bfloat16* pa = smb + cur * LB32;
#pragma unroll
        for (int kk = 0; kk < 2; kk++) {
            FAc ah[2], al[2];
#pragma unroll
            for (int i = 0; i < 2; i++) {
                wmma::load_matrix_sync(ah[i], pa + kk * 16 * LDG_ + wm * 32 + i * 16, LDG_);
                wmma::load_matrix_sync(al[i], pa + LT32 + kk * 16 * LDG_ + wm * 32 + i * 16, LDG_);
            }
            int krow = ci * 32 + kk * 16;
#pragma unroll
            for (int j = 0; j < 4; j++) {
                FBr bh, bl;
                wmma::load_matrix_sync(bh, SFhi + krow * LDG_ + wn * 64 + j * 16, LDG_);
                wmma::load_matrix_sync(bl, SFlo + krow * LDG_ + wn * 64 + j * 16, LDG_);
#pragma unroll
                for (int i = 0; i < 2; i++) {
                    wmma::mma_sync(acc[i][j], ah[i], bh, acc[i][j]);
                    wmma::mma_sync(acc[i][j], ah[i], bl, acc[i][j]);
                    wmma::mma_sync(acc[i][j], al[i], bh, acc[i][j]);
                }
            }
        }
        __syncthreads();
    }

    // ---- epilogue 2: gate + residual -> g_h planes, minmax (patch = buf0) ----
    float* patch2 = (float*)smb + w * 384;
    float mnv = INFINITY, mxv = -INFINITY;
#pragma unroll
    for (int i = 0; i < 2; i++) {
        int o = wm * 32 + i * 16 + r;
        float gadd = bias2[o] + g_g2v[(b * Wn + o) * SEGn + seg];
        float rc = g_rec[(b * Wn + o) * SEGn + seg];
#pragma unroll
        for (int j = 0; j < 4; j++) {
            wmma::store_matrix_sync(patch2, acc[i][j], 24, wmma::mem_row_major);
            __syncwarp();
            int lc = wn * 64 + j * 16 + c0;
            uint4 rh = *(const uint4*)(SFhi + o * LDG_ + lc);
            uint4 rl = *(const uint4*)(SFlo + o * LDG_ + lc);
            const __nv_bfloat16* hp = (const __nv_bfloat16*)&rh;
            const __nv_bfloat16* lp = (const __nv_bfloat16*)&rl;
            float vals[8];
#pragma unroll
            for (int jj = 0; jj < 8; jj++) {
                float fn = __bfloat162float(hp[jj]) + __bfloat162float(lp[jj]);
                float aa = patch2[r * 24 + c0 + jj] + gadd;
                float v = fn + rc / (1.0f + expf(-aa));
                vals[jj] = v;
                mnv = fminf(mnv, v); mxv = fmaxf(mxv, v);
            }
            long gi = ((long)(b * Wn + o)) * Ln + l0 + lc;
            split8_store(vals, &g_h_hi[gi], &g_h_lo[gi]);
            __syncwarp();
        }
    }
#pragma unroll
    for (int s = 16; s; s >>= 1) {
        mnv = fminf(mnv, __shfl_xor_sync(0xffffffffu, mnv, s));
        mxv = fmaxf(mxv, __shfl_xor_sync(0xffffffffu, mxv, s));
    }
    if (ln == 0) { redmn[w] = mnv; redmx[w] = mxv; }
    __syncthreads();
    if (tid == 0) {
        for (int q = 1; q < 8; q++) {
            mnv = fminf(mnv, redmn[q]); mxv = fmaxf(mxv, redmx[q]);
        }
        atomicMinF(&g_mn[seg], mnv);
        atomicMaxF(&g_mx[seg], mxv);
    }
}

// ---------------- fc1+fc2 fused (Round-12 version) ----------------
__global__ void __launch_bounds__(256) k_fc12(
        const float* __restrict__ bias, const float* __restrict__ w2,
        const float* __restrict__ b2, float* __restrict__ outp) {
    extern __shared__ __nv_bfloat16 smb[];
    __shared__ __align__(32) float patch[8][16][24];
    __shared__ float WP[8][16];
    const uint32_t sb = smem_u32(smb);

    const int b = blockIdx.y, l0 = blockIdx.x * 128;
    const int tid = threadIdx.x, w = tid >> 5, ln = tid & 31;
    const __nv_bfloat16* Whi = g_w_hi + (long)8 * Wn * Wn;
    const __nv_bfloat16* Wlo = g_w_lo + (long)8 * Wn * Wn;

    FC acc[8];
#pragma unroll
    for (int n = 0; n < 8; n++) wmma::fill_fragment(acc[n], 0.0f);

    auto stage_chunk = [&](int ci, int buf) {
        uint32_t base = sb + (uint32_t)buf * GEMM_BUF * 2;
        stage2(base, base + GEMM_TILE * 2,
               Whi + (long)ci * 16 * Wn, Wlo + (long)ci * 16 * Wn, Wn, 16, 16, LDG_);
        stage2(base + 2 * GEMM_TILE * 2, base + 3 * GEMM_TILE * 2,
               g_h_hi + ((long)(b * Wn + ci * 16)) * Ln + l0,
               g_h_lo + ((long)(b * Wn + ci * 16)) * Ln + l0, Ln, 16, 16, LDG_);
    };

    stage_chunk(0, 0);
    CP_COMMIT();
    for (int ci = 0; ci < 8; ci++) {
        int cur = ci & 1;
        if (ci < 7) {
            stage_chunk(ci + 1, cur ^ 1);
            CP_COMMIT();
            CP_WAIT1();
        } else {
            CP_WAIT0();
        }
        __syncthreads();
        const __nv_bfloat16* pa = smb + cur * GEMM_BUF;
        const __nv_bfloat16* pb = pa + 2 * GEMM_TILE;
        FAc ah, al;
        wmma::load_matrix_sync(ah, pa + w * 16, LDG_);
        wmma::load_matrix_sync(al, pa + GEMM_TILE + w * 16, LDG_);
#pragma unroll
        for (int n = 0; n < 8; n++) {
            FBr bh, bl;
            wmma::load_matrix_sync(bh, pb + n * 16, LDG_);
            wmma::load_matrix_sync(bl, pb + GEMM_TILE + n * 16, LDG_);
            wmma::mma_sync(acc[n], ah, bh, acc[n]);
            wmma::mma_sync(acc[n], ah, bl, acc[n]);
            wmma::mma_sync(acc[n], al, bh, acc[n]);
        }
        __syncthreads();
    }

    const int r = ln >> 1, c0 = (ln & 1) * 8;
    const int o = w * 16 + r;
    const float bi = bias[o], w2v = w2[o];
#pragma unroll
    for (int n = 0; n < 8; n++) {
        wmma::store_matrix_sync(&patch[w][0][0], acc[n], 24, wmma::mem_row_major);
        __syncwarp();
        float vals[8];
#pragma unroll
        for (int j = 0; j < 8; j++)
            vals[j] = gelu_exact(patch[w][r][c0 + j] + bi) * w2v;
#pragma unroll
        for (int s = 2; s <= 16; s <<= 1)
#pragma unroll
            for (int j = 0; j < 8; j++)
                vals[j] += __shfl_xor_sync(0xffffffffu, vals[j], s);
        if (ln < 2)
#pragma unroll
            for (int j = 0; j < 8; j++) WP[w][ln * 8 + j] = vals[j];
        __syncthreads();
        if (tid < 16) {
            float t = 0.f;
#pragma unroll
            for (int q = 0; q < 8; q++) t += WP[q][tid];
            outp[(long)b * Ln + l0 + n * 16 + tid] = t + b2[0];
        }
        __syncthreads();
    }
}

// ---------------- launch ----------------
extern "C" void kernel_launch(void* const* d_in, const int* in_sizes, int n_in,
                              void* d_out, int out_size) {
    const float* x       = (const float*)d_in[0];
    const float* fc0_w   = (const float*)d_in[1];
    const float* fc0_b   = (const float*)d_in[2];
    const float* spec_wr = (const float*)d_in[3];
    const float* spec_wi = (const float*)d_in[4];
    const float* conv_w  = (const float*)d_in[5];
    const float* conv_b  = (const float*)d_in[6];
    const float* cheb_w  = (const float*)d_in[7];
    const float* gate_w  = (const float*)d_in[8];
    const float* gate_b  = (const float*)d_in[9];
    const float* fc1_w   = (const float*)d_in[10];
    const float* fc1_b   = (const float*)d_in[11];
    const float* fc2_w   = (const float*)d_in[12];
    const float* fc2_b   = (const float*)d_in[13];

    cudaFuncSetAttribute(k_dft,   cudaFuncAttributeMaxDynamicSharedMemorySize, DFT_SMEM);
    cudaFuncSetAttribute(k_layer, cudaFuncAttributeMaxDynamicSharedMemorySize, LAYER_SMEM);
    cudaFuncSetAttribute(k_fc12,  cudaFuncAttributeMaxDynamicSharedMemorySize, FC_SMEM);

    k_init_mnmx<<<1, 32>>>();
    k_fc0<<<(Bn * Wn * Ln) / 2048, 256>>>(x, fc0_w, fc0_b);
    k_basis<<<(MODESn * Ln) / 256, 256>>>();
    k_dft<<<dim3(SPLITS, Bn), 256, DFT_SMEM>>>();     // layer 0 DFT
    k_wbar<<<NLn * SEGn * CMn, 128>>>(cheb_w);
    k_wsplit<<<(9 * Wn * Wn) / 256, 256>>>(conv_w, gate_w, fc1_w);

    for (int i = 0; i < NLn; i++) {
        if (i > 0) k_dft<<<dim3(SPLITS, Bn), 256, DFT_SMEM>>>();
        k_dft_reduce<<<(Bn * Wn * J2) / 256, 256>>>();
        k_modemix<<<dim3(16, Bn), 256>>>(spec_wr, spec_wi, i);
        k_chebg2<<<dim3(SEGn, Bn), 128>>>(gate_w, i);
        k_layer<<<dim3(Ln / 128, Bn), 256, LAYER_SMEM>>>(i, conv_b, gate_b);
    }
    k_fc12<<<dim3(Ln / 128, Bn), 256, FC_SMEM>>>(fc1_b, fc2_w, fc2_b, (float*)d_out);
}

// round 15
// speedup vs baseline: 1.1993x; 1.1402x over previous
#include <cuda_runtime.h>
#include <cuda_bf16.h>
#include <math.h>
#include <stdint.h>
#include <mma.h>

using namespace nvcuda;

#define Bn 8
#define Ln 8192
#define Wn 128
#define MODESn 32
#define NLn 4
#define SEGn 4
#define CMn 8
#define LSn 2048
#define J2 64
#define SPLITS 32
#define LDG_ 136                 // gemm smem tile stride (bf16 elems)
#define LDD_ 40                  // dft smem tile stride (bf16 elems)

#define GEMM_TILE (16 * LDG_)                 // 2176 elems
#define GEMM_BUF  (4 * GEMM_TILE)             // 8704 elems (Ahi Alo Bhi Blo)
#define SF_PLANE  (128 * LDG_)                // 17408 elems
#define LAYER_SMEM ((2 * GEMM_BUF + 2 * SF_PLANE) * 2)   // 104448 B
#define FC_SMEM   (2 * GEMM_BUF * 2)          // 34816 B
#define DFT_ATILE (128 * LDD_)                // 5120
#define DFT_BTILE (64 * LDD_)                 // 2560
#define DFT_BUF   (2 * DFT_ATILE + 2 * DFT_BTILE)  // 15360
#define DFT_SMEM  (2 * DFT_BUF * 2)           // 61440 B

typedef wmma::fragment<wmma::matrix_a,16,16,16,__nv_bfloat16,wmma::col_major> FAc;
typedef wmma::fragment<wmma::matrix_a,16,16,16,__nv_bfloat16,wmma::row_major> FAr;
typedef wmma::fragment<wmma::matrix_b,16,16,16,__nv_bfloat16,wmma::row_major> FBr;
typedef wmma::fragment<wmma::matrix_b,16,16,16,__nv_bfloat16,wmma::col_major> FBc;
typedef wmma::fragment<wmma::accumulator,16,16,16,float> FC;

// ---------------- device scratch: bf16 hi/lo planes ----------------
__device__ __nv_bfloat16 g_h_hi[Bn*Wn*Ln], g_h_lo[Bn*Wn*Ln];     // [b][c][l]
__device__ __nv_bfloat16 g_bas_hi[J2*Ln], g_bas_lo[J2*Ln];       // [j][l]
__device__ __nv_bfloat16 g_sp_hi[Bn*J2*Wn], g_sp_lo[Bn*J2*Wn];   // [b][j][o]
__device__ __nv_bfloat16 g_w_hi[9*Wn*Wn], g_w_lo[9*Wn*Wn];       // [m][c][o]
__device__ float g_part[SPLITS*Bn*Wn*J2];                        // 8 MB
__device__ float g_cpart[SPLITS*Bn*Wn*CMn];                      // 1 MB
__device__ float g_hf2[Bn*Wn*J2];
__device__ float g_rec[Bn*Wn*SEGn];
__device__ float g_g2v[Bn*Wn*SEGn];
__device__ float g_wbar[NLn*SEGn*CMn*Wn];
__device__ float g_mn[SEGn];
__device__ float g_mx[SEGn];

// ---------------- helpers ----------------
__device__ __forceinline__ float gelu_exact(float v) {
    return 0.5f * v * (1.0f + erff(v * 0.70710678118654752f));
}
__device__ __forceinline__ void split1(float v, __nv_bfloat16* hi, __nv_bfloat16* lo) {
    __nv_bfloat16 h = __float2bfloat16(v);
    *hi = h;
    *lo = __float2bfloat16(v - __bfloat162float(h));
}
__device__ __forceinline__ void split8_store(const float* v, __nv_bfloat16* hi,
                                             __nv_bfloat16* lo) {
    __nv_bfloat16 hb[8], lb[8];
#pragma unroll
    for (int j = 0; j < 8; j++) {
        __nv_bfloat16 h = __float2bfloat16(v[j]);
        hb[j] = h;
        lb[j] = __float2bfloat16(v[j] - __bfloat162float(h));
    }
    *(uint4*)hi = *(uint4*)hb;
    *(uint4*)lo = *(uint4*)lb;
}
__device__ __forceinline__ uint32_t smem_u32(const void* p) {
    uint32_t a;
    asm("{ .reg .u64 t; cvta.to.shared.u64 t, %1; cvt.u32.u64 %0, t; }" : "=r"(a) : "l"(p));
    return a;
}
__device__ __forceinline__ void cpa16(uint32_t s, const void* g) {
    asm volatile("cp.async.cg.shared.global [%0], [%1], 16;" :: "r"(s), "l"(g));
}
#define CP_COMMIT() asm volatile("cp.async.commit_group;" ::: "memory")
#define CP_WAIT1()  asm volatile("cp.async.wait_group 1;" ::: "memory")
#define CP_WAIT0()  asm volatile("cp.async.wait_group 0;" ::: "memory")

__device__ __forceinline__ void atomicMinF(float* addr, float v) {
    int* ia = (int*)addr; int old = *ia;
    while (__int_as_float(old) > v) {
        int assumed = old;
        old = atomicCAS(ia, assumed, __float_as_int(v));
        if (old == assumed) break;
    }
}
__device__ __forceinline__ void atomicMaxF(float* addr, float v) {
    int* ia = (int*)addr; int old = *ia;
    while (__int_as_float(old) < v) {
        int assumed = old;
        old = atomicCAS(ia, assumed, __float_as_int(v));
        if (old == assumed) break;
    }
}

// stage a hi/lo pair of tiles: rows x (c16*8 bf16), src stride in elems
__device__ __forceinline__ void stage2(uint32_t dhi, uint32_t dlo,
        const __nv_bfloat16* __restrict__ shi, const __nv_bfloat16* __restrict__ slo,
        long stride, int rows, int c16, int ld) {
    int n = rows * c16;
    for (int i = threadIdx.x; i < n; i += 256) {
        int r = i / c16, q = i - r * c16;
        uint32_t off = (uint32_t)(r * ld + q * 8) * 2;
        long gix = (long)r * stride + q * 8;
        cpa16(dhi + off, shi + gix);
        cpa16(dlo + off, slo + gix);
    }
}

// ---------------- small scalar kernels ----------------
__global__ void k_basis() {
    int t = blockIdx.x * blockDim.x + threadIdx.x;   // MODES*L
    int k = t / Ln, l = t % Ln;
    float x = (float)(k * l) * (1.0f / 4096.0f);
    float s, c;
    sincospif(x, &s, &c);
    split1(c, &g_bas_hi[k * Ln + l], &g_bas_lo[k * Ln + l]);
    split1(s, &g_bas_hi[(MODESn + k) * Ln + l], &g_bas_lo[(MODESn + k) * Ln + l]);
}

__global__ void k_wbar(const float* __restrict__ cheb_w) {
    int ism = blockIdx.x;
    int c = threadIdx.x;
    const float* p = cheb_w + ((long)ism * Wn + c) * Wn;
    float s = 0.f;
    for (int o = 0; o < Wn; o++) s += p[o];
    g_wbar[ism * Wn + c] = s * (1.0f / Wn);
}

__global__ void k_wsplit(const float* __restrict__ conv_w,
                         const float* __restrict__ gate_w,
                         const float* __restrict__ fc1_w) {
    int t = blockIdx.x * 256 + threadIdx.x;   // 9*128*128
    int m = t >> 14;
    int co = t & 16383;
    float v;
    if (m < 4)      v = conv_w[(long)m * 16384 + co];
    else if (m < 8) v = gate_w[(long)(m - 4) * 32768 + co];
    else            v = fc1_w[co];
    split1(v, &g_w_hi[t], &g_w_lo[t]);
}

__global__ void k_init_mnmx() {
    if (threadIdx.x < SEGn) { g_mn[threadIdx.x] = INFINITY; g_mx[threadIdx.x] = -INFINITY; }
}

// fc0 -> h planes [b][c][l], fused per-segment minmax
__global__ void k_fc0(const float* __restrict__ x, const float* __restrict__ w,
                      const float* __restrict__ bias) {
    __shared__ float smn[8], smx[8];
    long base = (long)blockIdx.x * 2048;
    float mn = INFINITY, mx = -INFINITY;
#pragma unroll
    for (int it = 0; it < 8; it++) {
        long t = base + it * 256 + threadIdx.x;
        int l = (int)(t & (Ln - 1));
        long bc = t >> 13;
        int c = (int)(bc & 127);
        long xb = ((bc >> 7) * Ln + l) * 2;
        float v = x[xb] * w[c] + x[xb + 1] * w[Wn + c] + bias[c];
        split1(v, &g_h_hi[t], &g_h_lo[t]);
        mn = fminf(mn, v); mx = fmaxf(mx, v);
    }
#pragma unroll
    for (int o = 16; o; o >>= 1) {
        mn = fminf(mn, __shfl_xor_sync(0xffffffffu, mn, o));
        mx = fmaxf(mx, __shfl_xor_sync(0xffffffffu, mx, o));
    }
    if ((threadIdx.x & 31) == 0) { smn[threadIdx.x >> 5] = mn; smx[threadIdx.x >> 5] = mx; }
    __syncthreads();
    if (threadIdx.x == 0) {
        for (int q = 1; q < 8; q++) { mn = fminf(mn, smn[q]); mx = fmaxf(mx, smx[q]); }
        int seg = (int)((base >> 11) & 3);
        atomicMinF(&g_mn[seg], mn);
        atomicMaxF(&g_mx[seg], mx);
    }
}

__global__ void k_dft_reduce() {
    int t = blockIdx.x * 256 + threadIdx.x;
    float s = 0.f;
#pragma unroll
    for (int q = 0; q < SPLITS; q++) s += g_part[(long)q * (Bn * Wn * J2) + t];
    g_hf2[t] = s;
}

__global__ void k_modemix(const float* __restrict__ wr, const float* __restrict__ wi,
                          int layer) {
    int b = blockIdx.y;
    int o = blockIdx.x * 8 + (threadIdx.x >> 5);
    int k = threadIdx.x & 31;
    const float* wrp = wr + (long)layer * Wn * Wn * MODESn;
    const float* wip = wi + (long)layer * Wn * Wn * MODESn;
    float omr = 0.f, omi = 0.f;
    for (int i = 0; i < Wn; i++) {
        float fr = g_hf2[(b * Wn + i) * J2 + k];
        float fs = g_hf2[(b * Wn + i) * J2 + 32 + k];
        long wix = ((long)i * Wn + o) * MODESn + k;
        float a = wrp[wix], bb = wip[wix];
        omr += fr * a + fs * bb;
        omi += fr * bb - fs * a;
    }
    float scale = ((k == 0) ? 1.0f : 2.0f) * (1.0f / Ln);
    int i0 = (b * J2 + k) * Wn + o;
    int i1 = (b * J2 + 32 + k) * Wn + o;
    split1(scale * omr, &g_sp_hi[i0], &g_sp_lo[i0]);
    split1(-scale * omi, &g_sp_hi[i1], &g_sp_lo[i1]);
}

// cheb reduce over splits + tanh -> rec, then g2 GEMV; also re-inits mn/mx
__global__ void k_chebg2(const float* __restrict__ gate_w, int layer) {
    __shared__ float srec[Wn];
    int s = blockIdx.x, b = blockIdx.y;
    int c = threadIdx.x;
    float a[CMn];
#pragma unroll
    for (int m = 0; m < CMn; m++) a[m] = 0.f;
#pragma unroll
    for (int sp = 0; sp < 8; sp++) {
        int split = s * 8 + sp;
        const float* pp = g_cpart + (((long)split * Bn + b) * Wn + c) * CMn;
        float4 v0 = *(const float4*)pp;
        float4 v1 = *(const float4*)(pp + 4);
        a[0] += v0.x; a[1] += v0.y; a[2] += v0.z; a[3] += v0.w;
        a[4] += v1.x; a[5] += v1.y; a[6] += v1.z; a[7] += v1.w;
    }
    float r = 0.f;
#pragma unroll
    for (int m = 0; m < CMn; m++)
        r += (a[m] * (1.0f / LSn)) * g_wbar[((layer * SEGn + s) * CMn + m) * Wn + c];
    float rec = tanhf(r);
    srec[c] = rec;
    g_rec[(b * Wn + c) * SEGn + s] = rec;
    if (blockIdx.x == 0 && blockIdx.y == 0 && c < SEGn) {
        g_mn[c] = INFINITY; g_mx[c] = -INFINITY;
    }
    __syncthreads();
    int o = c;
    const float* gw = gate_w + (long)layer * 2 * Wn * Wn + Wn * Wn;
    float acc = 0.f;
#pragma unroll 4
    for (int cc = 0; cc < Wn; cc++)
        acc += srec[cc] * gw[cc * Wn + o];
    g_g2v[(b * Wn + o) * SEGn + s] = acc;
}

// ---------------- DFT + fused cheb partials ----------------
__global__ void __launch_bounds__(256, 2) k_dft() {
    extern __shared__ __nv_bfloat16 smb[];
    const uint32_t sb = smem_u32(smb);
    const int split = blockIdx.x, b = blockIdx.y;
    const int tid = threadIdx.x;
    const int w = tid >> 5;
    const int wm = w >> 1, wn = w & 1;
    const long lbase = (long)split * 256;
    const int seg = split >> 3;
    const int cch = tid >> 1, half = tid & 1;   // cheb mapping
    const float mnv = g_mn[seg];
    const float scv = 2.0f / (g_mx[seg] - mnv);

    FC acc[2][2];
#pragma unroll
    for (int i = 0; i < 2; i++)
#pragma unroll
        for (int j = 0; j < 2; j++) wmma::fill_fragment(acc[i][j], 0.0f);
    float a[CMn];
#pragma unroll
    for (int m = 0; m < CMn; m++) a[m] = 0.f;

    auto stage_chunk = [&](int ci, int buf) {
        uint32_t base = sb + (uint32_t)buf * DFT_BUF * 2;
        long l0c = lbase + ci * 32;
        stage2(base, base + DFT_ATILE * 2,
               g_h_hi + ((long)b * Wn) * Ln + l0c, g_h_lo + ((long)b * Wn) * Ln + l0c,
               Ln, 128, 4, LDD_);
        stage2(base + 2 * DFT_ATILE * 2, base + 2 * DFT_ATILE * 2 + DFT_BTILE * 2,
               g_bas_hi + l0c, g_bas_lo + l0c, Ln, 64, 4, LDD_);
    };

    stage_chunk(0, 0);
    CP_COMMIT();
    for (int ci = 0; ci < 8; ci++) {
        int cur = ci & 1;
        if (ci < 7) {
            stage_chunk(ci + 1, cur ^ 1);
            CP_COMMIT();
            CP_WAIT1();
        } else {
            CP_WAIT0();
        }
        __syncthreads();
        const __nv_bfloat16* pa = smb + cur * DFT_BUF;
        const __nv_bfloat16* pb = pa + 2 * DFT_ATILE;
#pragma unroll
        for (int ks = 0; ks < 2; ks++) {
            FAr ah[2], al[2];
#pragma unroll
            for (int i = 0; i < 2; i++) {
                wmma::load_matrix_sync(ah[i], pa + (wm * 32 + i * 16) * LDD_ + ks * 16, LDD_);
                wmma::load_matrix_sync(al[i], pa + DFT_ATILE + (wm * 32 + i * 16) * LDD_ + ks * 16, LDD_);
            }
#pragma unroll
            for (int j = 0; j < 2; j++) {
                FBc bh, bl;
                wmma::load_matrix_sync(bh, pb + (wn * 32 + j * 16) * LDD_ + ks * 16, LDD_);
                wmma::load_matrix_sync(bl, pb + DFT_BTILE + (wn * 32 + j * 16) * LDD_ + ks * 16, LDD_);
#pragma unroll
                for (int i = 0; i < 2; i++) {
                    wmma::mma_sync(acc[i][j], ah[i], bh, acc[i][j]);
                    wmma::mma_sync(acc[i][j], ah[i], bl, acc[i][j]);
                    wmma::mma_sync(acc[i][j], al[i], bh, acc[i][j]);
                }
            }
        }
        // cheb partial pass over the same staged chunk (c = cch, 16 l values)
        {
            const __nv_bfloat16* hrow = pa + cch * LDD_ + half * 16;
            const __nv_bfloat16* lrow = hrow + DFT_ATILE;
#pragma unroll
            for (int j = 0; j < 16; j++) {
                float v = __bfloat162float(hrow[j]) + __bfloat162float(lrow[j]);
                float xn = (v - mnv) * scv - 1.0f;
                float Tpp = 1.0f, Tp = xn;
                a[0] += xn;
                a[1] += xn * xn;
#pragma unroll
                for (int m = 2; m < CMn; m++) {
                    float Tn = 2.0f * xn * Tp - Tpp;
                    a[m] += xn * Tn;
                    Tpp = Tp; Tp = Tn;
                }
            }
        }
        __syncthreads();
    }
#pragma unroll
    for (int m = 0; m < CMn; m++) a[m] += __shfl_xor_sync(0xffffffffu, a[m], 1);
    if (half == 0) {
        float* dst = g_cpart + (((long)split * Bn + b) * Wn + cch) * CMn;
        *(float4*)dst = make_float4(a[0], a[1], a[2], a[3]);
        *(float4*)(dst + 4) = make_float4(a[4], a[5], a[6], a[7]);
    }
#pragma unroll
    for (int i = 0; i < 2; i++)
#pragma unroll
        for (int j = 0; j < 2; j++)
            wmma::store_matrix_sync(
                g_part + (((long)split * Bn + b) * Wn + wm * 32 + i * 16) * J2 + wn * 32 + j * 16,
                acc[i][j], J2, wmma::mem_row_major);
}

// ---------------- fused layer kernel (104 KB smem, 2 CTAs/SM) ----------------
__global__ void __launch_bounds__(256, 2) k_layer(int layer,
        const float* __restrict__ conv_b, const float* __restrict__ gate_b) {
    extern __shared__ __nv_bfloat16 smb[];
    __shared__ float redmn[8], redmx[8];
    const uint32_t sb = smem_u32(smb);
    __nv_bfloat16* SFhi = smb + 2 * GEMM_BUF;
    __nv_bfloat16* SFlo = SFhi + SF_PLANE;

    const int b = blockIdx.y, l0 = blockIdx.x * 128;
    const int tid = threadIdx.x, w = tid >> 5, ln = tid & 31;
    const int wm = w >> 1, wn = w & 1;
    const int seg = l0 >> 11;
    const int r = ln >> 1, c0 = (ln & 1) * 8;
    const float* bias1 = conv_b + (long)layer * Wn;
    const float* bias2 = gate_b + (long)layer * Wn;
    const __nv_bfloat16* W1hi = g_w_hi + (long)layer * Wn * Wn;
    const __nv_bfloat16* W1lo = g_w_lo + (long)layer * Wn * Wn;
    const __nv_bfloat16* W2hi = g_w_hi + (long)(4 + layer) * Wn * Wn;
    const __nv_bfloat16* W2lo = g_w_lo + (long)(4 + layer) * Wn * Wn;

    FC acc[2][4];
#pragma unroll
    for (int i = 0; i < 2; i++)
#pragma unroll
        for (int j = 0; j < 4; j++) wmma::fill_fragment(acc[i][j], 0.0f);

    auto stage1 = [&](int ci, int buf) {
        uint32_t base = sb + (uint32_t)buf * GEMM_BUF * 2;
        const __nv_bfloat16 *ah, *al, *bh, *bl;
        if (ci < 8) {
            ah = W1hi + (long)ci * 16 * Wn; al = W1lo + (long)ci * 16 * Wn;
            bh = g_h_hi + ((long)(b * Wn + ci * 16)) * Ln + l0;
            bl = g_h_lo + ((long)(b * Wn + ci * 16)) * Ln + l0;
        } else {
            ah = g_sp_hi + ((long)b * J2 + (ci - 8) * 16) * Wn;
            al = g_sp_lo + ((long)b * J2 + (ci - 8) * 16) * Wn;
            bh = g_bas_hi + (long)((ci - 8) * 16) * Ln + l0;
            bl = g_bas_lo + (long)((ci - 8) * 16) * Ln + l0;
        }
        stage2(base, base + GEMM_TILE * 2, ah, al, Wn, 16, 16, LDG_);
        stage2(base + 2 * GEMM_TILE * 2, base + 3 * GEMM_TILE * 2, bh, bl, Ln, 16, 16, LDG_);
    };

    // ---- part 1 mainloop: K = 192 (12 chunks) ----
    stage1(0, 0);
    CP_COMMIT();
    for (int ci = 0; ci < 12; ci++) {
        int cur = ci & 1;
        if (ci < 11) {
            stage1(ci + 1, cur ^ 1);
            CP_COMMIT();
            CP_WAIT1();
        } else {
            CP_WAIT0();
        }
        __syncthreads();
        const __nv_bfloat16* pa = smb + cur * GEMM_BUF;
        const __nv_bfloat16* pb = pa + 2 * GEMM_TILE;
        FAc ah[2], al[2];
#pragma unroll
        for (int i = 0; i < 2; i++) {
            wmma::load_matrix_sync(ah[i], pa + wm * 32 + i * 16, LDG_);
            wmma::load_matrix_sync(al[i], pa + GEMM_TILE + wm * 32 + i * 16, LDG_);
        }
#pragma unroll
        for (int j = 0; j < 4; j++) {
            FBr bh, bl;
            wmma::load_matrix_sync(bh, pb + wn * 64 + j * 16, LDG_);
            wmma::load_matrix_sync(bl, pb + GEMM_TILE + wn * 64 + j * 16, LDG_);
#pragma unroll
            for (int i = 0; i < 2; i++) {
                wmma::mma_sync(acc[i][j], ah[i], bh, acc[i][j]);
                wmma::mma_sync(acc[i][j], ah[i], bl, acc[i][j]);
                wmma::mma_sync(acc[i][j], al[i], bh, acc[i][j]);
            }
        }
        __syncthreads();
    }

    // prefetch gate chunk 0 into buf0 (A slots)
    stage2(sb, sb + GEMM_TILE * 2, W2hi, W2lo, Wn, 16, 16, LDG_);
    CP_COMMIT();

    // ---- epilogue 1: gelu -> SF smem tile (patch area = buf1 floats) ----
    {
        float* patchw = (float*)(smb + GEMM_BUF) + w * 384;
#pragma unroll
        for (int i = 0; i < 2; i++) {
            int o = wm * 32 + i * 16 + r;
            float bi = bias1[o];
#pragma unroll
            for (int j = 0; j < 4; j++) {
                wmma::store_matrix_sync(patchw, acc[i][j], 24, wmma::mem_row_major);
                __syncwarp();
                float vals[8];
#pragma unroll
                for (int jj = 0; jj < 8; jj++)
                    vals[jj] = gelu_exact(patchw[r * 24 + c0 + jj] + bi);
                int lc = wn * 64 + j * 16 + c0;
                split8_store(vals, SFhi + o * LDG_ + lc, SFlo + o * LDG_ + lc);
                __syncwarp();
            }
        }
    }
    __syncthreads();

    // ---- part 2 mainloop: gate GEMM, B from SF smem (8 chunks) ----
#pragma unroll
    for (int i = 0; i < 2; i++)
#pragma unroll
        for (int j = 0; j < 4; j++) wmma::fill_fragment(acc[i][j], 0.0f);

    for (int ci = 0; ci < 8; ci++) {
        int cur = ci & 1;
        if (ci < 7) {
            uint32_t base = sb + (uint32_t)(cur ^ 1) * GEMM_BUF * 2;
            stage2(base, base + GEMM_TILE * 2,
                   W2hi + (long)(ci + 1) * 16 * Wn, W2lo + (long)(ci + 1) * 16 * Wn,
                   Wn, 16, 16, LDG_);
            CP_COMMIT();
            CP_WAIT1();
        } else {
            CP_WAIT0();
        }
        __syncthreads();
        const __nv_bfloat16* pa = smb + cur * GEMM_BUF;
        FAc ah[2], al[2];
#pragma unroll
        for (int i = 0; i < 2; i++) {
            wmma::load_matrix_sync(ah[i], pa + wm * 32 + i * 16, LDG_);
            wmma::load_matrix_sync(al[i], pa + GEMM_TILE + wm * 32 + i * 16, LDG_);
        }
#pragma unroll
        for (int j = 0; j < 4; j++) {
            FBr bh, bl;
            wmma::load_matrix_sync(bh, SFhi + ci * 16 * LDG_ + wn * 64 + j * 16, LDG_);
            wmma::load_matrix_sync(bl, SFlo + ci * 16 * LDG_ + wn * 64 + j * 16, LDG_);
#pragma unroll
            for (int i = 0; i < 2; i++) {
                wmma::mma_sync(acc[i][j], ah[i], bh, acc[i][j]);
                wmma::mma_sync(acc[i][j], ah[i], bl, acc[i][j]);
                wmma::mma_sync(acc[i][j], al[i], bh, acc[i][j]);
            }
        }
        __syncthreads();
    }

    // ---- epilogue 2: gate + residual -> g_h planes, minmax (patch = buf0) ----
    float* patch2 = (float*)smb + w * 384;
    float mnv = INFINITY, mxv = -INFINITY;
#pragma unroll
    for (int i = 0; i < 2; i++) {
        int o = wm * 32 + i * 16 + r;
        float gadd = bias2[o] + g_g2v[(b * Wn + o) * SEGn + seg];
        float rc = g_rec[(b * Wn + o) * SEGn + seg];
#pragma unroll
        for (int j = 0; j < 4; j++) {
            wmma::store_matrix_sync(patch2, acc[i][j], 24, wmma::mem_row_major);
            __syncwarp();
            int lc = wn * 64 + j * 16 + c0;
            uint4 rh = *(const uint4*)(SFhi + o * LDG_ + lc);
            uint4 rl = *(const uint4*)(SFlo + o * LDG_ + lc);
            const __nv_bfloat16* hp = (const __nv_bfloat16*)&rh;
            const __nv_bfloat16* lp = (const __nv_bfloat16*)&rl;
            float vals[8];
#pragma unroll
            for (int jj = 0; jj < 8; jj++) {
                float fn = __bfloat162float(hp[jj]) + __bfloat162float(lp[jj]);
                float aa = patch2[r * 24 + c0 + jj] + gadd;
                float v = fn + rc / (1.0f + expf(-aa));
                vals[jj] = v;
                mnv = fminf(mnv, v); mxv = fmaxf(mxv, v);
            }
            long gi = ((long)(b * Wn + o)) * Ln + l0 + lc;
            split8_store(vals, &g_h_hi[gi], &g_h_lo[gi]);
            __syncwarp();
        }
    }
#pragma unroll
    for (int s = 16; s; s >>= 1) {
        mnv = fminf(mnv, __shfl_xor_sync(0xffffffffu, mnv, s));
        mxv = fmaxf(mxv, __shfl_xor_sync(0xffffffffu, mxv, s));
    }
    if (ln == 0) { redmn[w] = mnv; redmx[w] = mxv; }
    __syncthreads();
    if (tid == 0) {
        for (int q = 1; q < 8; q++) {
            mnv = fminf(mnv, redmn[q]); mxv = fmaxf(mxv, redmx[q]);
        }
        atomicMinF(&g_mn[seg], mnv);
        atomicMaxF(&g_mx[seg], mxv);
    }
}

// ---------------- fc1+fc2 fused ----------------
__global__ void __launch_bounds__(256, 2) k_fc12(
        const float* __restrict__ bias, const float* __restrict__ w2,
        const float* __restrict__ b2, float* __restrict__ outp) {
    extern __shared__ __nv_bfloat16 smb[];
    __shared__ __align__(32) float patch[8][16][24];
    __shared__ float WP[8][16];
    const uint32_t sb = smem_u32(smb);

    const int b = blockIdx.y, l0 = blockIdx.x * 128;
    const int tid = threadIdx.x, w = tid >> 5, ln = tid & 31;
    const __nv_bfloat16* Whi = g_w_hi + (long)8 * Wn * Wn;
    const __nv_bfloat16* Wlo = g_w_lo + (long)8 * Wn * Wn;

    FC acc[8];
#pragma unroll
    for (int n = 0; n < 8; n++) wmma::fill_fragment(acc[n], 0.0f);

    auto stage_chunk = [&](int ci, int buf) {
        uint32_t base = sb + (uint32_t)buf * GEMM_BUF * 2;
        stage2(base, base + GEMM_TILE * 2,
               Whi + (long)ci * 16 * Wn, Wlo + (long)ci * 16 * Wn, Wn, 16, 16, LDG_);
        stage2(base + 2 * GEMM_TILE * 2, base + 3 * GEMM_TILE * 2,
               g_h_hi + ((long)(b * Wn + ci * 16)) * Ln + l0,
               g_h_lo + ((long)(b * Wn + ci * 16)) * Ln + l0, Ln, 16, 16, LDG_);
    };

    stage_chunk(0, 0);
    CP_COMMIT();
    for (int ci = 0; ci < 8; ci++) {
        int cur = ci & 1;
        if (ci < 7) {
            stage_chunk(ci + 1, cur ^ 1);
            CP_COMMIT();
            CP_WAIT1();
        } else {
            CP_WAIT0();
        }
        __syncthreads();
        const __nv_bfloat16* pa = smb + cur * GEMM_BUF;
        const __nv_bfloat16* pb = pa + 2 * GEMM_TILE;
        FAc ah, al;
        wmma::load_matrix_sync(ah, pa + w * 16, LDG_);
        wmma::load_matrix_sync(al, pa + GEMM_TILE + w * 16, LDG_);
#pragma unroll
        for (int n = 0; n < 8; n++) {
            FBr bh, bl;
            wmma::load_matrix_sync(bh, pb + n * 16, LDG_);
            wmma::load_matrix_sync(bl, pb + GEMM_TILE + n * 16, LDG_);
            wmma::mma_sync(acc[n], ah, bh, acc[n]);
            wmma::mma_sync(acc[n], ah, bl, acc[n]);
            wmma::mma_sync(acc[n], al, bh, acc[n]);
        }
        __syncthreads();
    }

    const int r = ln >> 1, c0 = (ln & 1) * 8;
    const int o = w * 16 + r;
    const float bi = bias[o], w2v = w2[o];
#pragma unroll
    for (int n = 0; n < 8; n++) {
        wmma::store_matrix_sync(&patch[w][0][0], acc[n], 24, wmma::mem_row_major);
        __syncwarp();
        float vals[8];
#pragma unroll
        for (int j = 0; j < 8; j++)
            vals[j] = gelu_exact(patch[w][r][c0 + j] + bi) * w2v;
#pragma unroll
        for (int s = 2; s <= 16; s <<= 1)
#pragma unroll
            for (int j = 0; j < 8; j++)
                vals[j] += __shfl_xor_sync(0xffffffffu, vals[j], s);
        if (ln < 2)
#pragma unroll
            for (int j = 0; j < 8; j++) WP[w][ln * 8 + j] = vals[j];
        __syncthreads();
        if (tid < 16) {
            float t = 0.f;
#pragma unroll
            for (int q = 0; q < 8; q++) t += WP[q][tid];
            outp[(long)b * Ln + l0 + n * 16 + tid] = t + b2[0];
        }
        __syncthreads();
    }
}

// ---------------- launch ----------------
extern "C" void kernel_launch(void* const* d_in, const int* in_sizes, int n_in,
                              void* d_out, int out_size) {
    const float* x       = (const float*)d_in[0];
    const float* fc0_w   = (const float*)d_in[1];
    const float* fc0_b   = (const float*)d_in[2];
    const float* spec_wr = (const float*)d_in[3];
    const float* spec_wi = (const float*)d_in[4];
    const float* conv_w  = (const float*)d_in[5];
    const float* conv_b  = (const float*)d_in[6];
    const float* cheb_w  = (const float*)d_in[7];
    const float* gate_w  = (const float*)d_in[8];
    const float* gate_b  = (const float*)d_in[9];
    const float* fc1_w   = (const float*)d_in[10];
    const float* fc1_b   = (const float*)d_in[11];
    const float* fc2_w   = (const float*)d_in[12];
    const float* fc2_b   = (const float*)d_in[13];

    cudaFuncSetAttribute(k_dft,   cudaFuncAttributeMaxDynamicSharedMemorySize, DFT_SMEM);
    cudaFuncSetAttribute(k_layer, cudaFuncAttributeMaxDynamicSharedMemorySize, LAYER_SMEM);
    cudaFuncSetAttribute(k_fc12,  cudaFuncAttributeMaxDynamicSharedMemorySize, FC_SMEM);

    k_init_mnmx<<<1, 32>>>();
    k_fc0<<<(Bn * Wn * Ln) / 2048, 256>>>(x, fc0_w, fc0_b);
    k_basis<<<(MODESn * Ln) / 256, 256>>>();
    k_dft<<<dim3(SPLITS, Bn), 256, DFT_SMEM>>>();     // layer 0 DFT
    k_wbar<<<NLn * SEGn * CMn, 128>>>(cheb_w);
    k_wsplit<<<(9 * Wn * Wn) / 256, 256>>>(conv_w, gate_w, fc1_w);

    for (int i = 0; i < NLn; i++) {
        if (i > 0) k_dft<<<dim3(SPLITS, Bn), 256, DFT_SMEM>>>();
        k_dft_reduce<<<(Bn * Wn * J2) / 256, 256>>>();
        k_modemix<<<dim3(16, Bn), 256>>>(spec_wr, spec_wi, i);
        k_chebg2<<<dim3(SEGn, Bn), 128>>>(gate_w, i);
        k_layer<<<dim3(Ln / 128, Bn), 256, LAYER_SMEM>>>(i, conv_b, gate_b);
    }
    k_fc12<<<dim3(Ln / 128, Bn), 256, FC_SMEM>>>(fc1_b, fc2_w, fc2_b, (float*)d_out);
}